// round 2
// baseline (speedup 1.0000x reference)
#include <cuda_runtime.h>

#define BATCH 32
#define HW 307200            // 480*640
#define HW4 (HW/4)           // 76800 float4 per channel per batch
#define GRID 888             // 148 SMs * 6 blocks -- guaranteed co-resident via launch_bounds
#define P2B 27               // blocks per batch (27*32 = 864 active blocks)
#define ACTIVE (P2B*BATCH)   // 864
#define CHUNK 2845           // ceil(76800/27); last block of each batch is short

__device__ float g_partial[ACTIVE];
__device__ volatile unsigned int g_arrive;

__device__ __forceinline__ void grid_sync()
{
    __syncthreads();
    if (threadIdx.x == 0) {
        __threadfence();
        unsigned int old = atomicAdd((unsigned int*)&g_arrive, 1u);
        unsigned int target = (old / GRID + 1u) * GRID;
        while (g_arrive < target) { __nanosleep(64); }
        __threadfence();
    }
    __syncthreads();
}

__device__ __forceinline__ void px_proc(float r, float g, float bl,
                                        float bf, float cf, float sf, float hf,
                                        float mean,
                                        float& ro, float& go, float& bo)
{
    // brightness
    r  = __saturatef(r * bf);
    g  = __saturatef(g * bf);
    bl = __saturatef(bl * bf);
    // contrast (blend with per-batch mean gray)
    float omcf = 1.0f - cf;
    r  = __saturatef(cf * r + omcf * mean);
    g  = __saturatef(cf * g + omcf * mean);
    bl = __saturatef(cf * bl + omcf * mean);
    // saturation (blend with per-pixel gray)
    float gray = 0.299f * r + 0.587f * g + 0.114f * bl;
    float omsf = 1.0f - sf;
    r  = __saturatef(sf * r + omsf * gray);
    g  = __saturatef(sf * g + omsf * gray);
    bl = __saturatef(sf * bl + omsf * gray);
    // hue: RGB -> HSV
    float maxc = fmaxf(r, fmaxf(g, bl));
    float minc = fminf(r, fminf(g, bl));
    float v = maxc;
    float cr = maxc - minc;
    float crd = (cr == 0.0f) ? 1.0f : cr;
    float s = cr / ((maxc == 0.0f) ? 1.0f : maxc);
    float inv_crd = 1.0f / crd;
    float rc = (maxc - r) * inv_crd;
    float gc = (maxc - g) * inv_crd;
    float bc = (maxc - bl) * inv_crd;
    float h;
    if (maxc == r)       h = bc - gc;            // hr branch
    else if (maxc == g)  h = 2.0f + rc - bc;     // hg branch
    else                 h = 4.0f + gc - rc;     // hb branch
    h = h * (1.0f / 6.0f);
    h = h - floorf(h);        // python-style mod 1
    h = h + hf;
    h = h - floorf(h);
    // HSV -> RGB
    float i6 = h * 6.0f;
    float fi = floorf(i6);
    float f = i6 - fi;
    int i = ((int)fi) % 6;    // guards h==1.0 rounding edge
    float p = v * (1.0f - s);
    float q = v * (1.0f - f * s);
    float t = v * (1.0f - (1.0f - f) * s);
    switch (i) {
        case 0:  ro = v; go = t; bo = p; break;
        case 1:  ro = q; go = v; bo = p; break;
        case 2:  ro = p; go = v; bo = t; break;
        case 3:  ro = p; go = q; bo = v; break;
        case 4:  ro = t; go = p; bo = v; break;
        default: ro = v; go = p; bo = q; break;
    }
}

__global__ void __launch_bounds__(256, 6)
cr_fused_kernel(const float* __restrict__ x,
                const float* __restrict__ bf_arr,
                const float* __restrict__ cf_arr,
                const float* __restrict__ sf_arr,
                const float* __restrict__ hf_arr,
                float* __restrict__ out)
{
    int blk = blockIdx.x;
    bool active = (blk < ACTIVE);
    int b   = active ? (blk / P2B) : 0;
    int sub = active ? (blk % P2B) : 0;

    int start4 = sub * CHUNK;
    int end4   = min(start4 + CHUNK, HW4);

    size_t base = (size_t)b * 3 * HW;
    const float4* px = (const float4*)(x + base);

    // ---------- Phase 1: partial gray sum of clip(x*bf) over this block's chunk ----------
    if (active) {
        float bf = bf_arr[b];
        float acc = 0.0f;
        for (int i = start4 + threadIdx.x; i < end4; i += 256) {
            float4 r  = px[i];
            float4 g  = px[i + HW4];
            float4 bl = px[i + 2 * HW4];
            float rr = __saturatef(r.x * bf) + __saturatef(r.y * bf)
                     + __saturatef(r.z * bf) + __saturatef(r.w * bf);
            float gg = __saturatef(g.x * bf) + __saturatef(g.y * bf)
                     + __saturatef(g.z * bf) + __saturatef(g.w * bf);
            float bb = __saturatef(bl.x * bf) + __saturatef(bl.y * bf)
                     + __saturatef(bl.z * bf) + __saturatef(bl.w * bf);
            acc += 0.299f * rr + 0.587f * gg + 0.114f * bb;
        }
        __shared__ float s[256];
        s[threadIdx.x] = acc;
        __syncthreads();
        #pragma unroll
        for (int off = 128; off > 0; off >>= 1) {
            if (threadIdx.x < off) s[threadIdx.x] += s[threadIdx.x + off];
            __syncthreads();
        }
        if (threadIdx.x == 0) g_partial[blk] = s[0];
    }

    // ---------- Grid-wide barrier ----------
    grid_sync();

    if (!active) return;

    // ---------- Phase 2: fused elementwise; chunk re-read mostly hits L2 ----------
    __shared__ float sm[5];
    if (threadIdx.x == 0) {
        float sum = 0.0f;
        #pragma unroll
        for (int i = 0; i < P2B; i++) sum += g_partial[b * P2B + i];
        sm[0] = sum * (1.0f / (float)HW);
        sm[1] = bf_arr[b];
        sm[2] = cf_arr[b];
        sm[3] = sf_arr[b];
        sm[4] = hf_arr[b];
    }
    __syncthreads();
    float mean = sm[0], bf = sm[1], cf = sm[2], sf = sm[3], hf = sm[4];

    float4* pox = (float4*)(out + base);

    for (int i = start4 + threadIdx.x; i < end4; i += 256) {
        float4 R  = px[i];
        float4 G  = px[i + HW4];
        float4 Bv = px[i + 2 * HW4];

        float4 Ro, Go, Bo;
        px_proc(R.x, G.x, Bv.x, bf, cf, sf, hf, mean, Ro.x, Go.x, Bo.x);
        px_proc(R.y, G.y, Bv.y, bf, cf, sf, hf, mean, Ro.y, Go.y, Bo.y);
        px_proc(R.z, G.z, Bv.z, bf, cf, sf, hf, mean, Ro.z, Go.z, Bo.z);
        px_proc(R.w, G.w, Bv.w, bf, cf, sf, hf, mean, Ro.w, Go.w, Bo.w);

        pox[i]           = Ro;
        pox[i + HW4]     = Go;
        pox[i + 2 * HW4] = Bo;
    }
}

extern "C" void kernel_launch(void* const* d_in, const int* in_sizes, int n_in,
                              void* d_out, int out_size)
{
    const float* x  = (const float*)d_in[0];
    const float* bf = (const float*)d_in[1];
    const float* cf = (const float*)d_in[2];
    const float* sf = (const float*)d_in[3];
    const float* hf = (const float*)d_in[4];
    float* out = (float*)d_out;

    cr_fused_kernel<<<GRID, 256>>>(x, bf, cf, sf, hf, out);
}

// round 3
// speedup vs baseline: 1.1469x; 1.1469x over previous
#include <cuda_runtime.h>

#define BATCH 32
#define HW 307200            // 480*640
#define HW4 (HW/4)           // 76800 float4 per channel per batch
#define NBLK 40              // reduction blocks per batch -> 1280 total
#define CHUNK4 (HW4/NBLK)    // 1920 float4 per reduction block
#define BLKS_PER_BATCH 300   // HW4 / 256

__device__ float g_partial[BATCH * NBLK];

// ---------------- Pass 1: per-batch gray sum of clip(x*bf) ----------------
__global__ void __launch_bounds__(256)
cr_reduce_kernel(const float* __restrict__ x, const float* __restrict__ bf_arr)
{
    int blk = blockIdx.x;          // 0 .. BATCH*NBLK-1
    int b   = blk / NBLK;
    int sub = blk % NBLK;
    float bf = bf_arr[b];

    const float4* base = (const float4*)(x + (size_t)b * 3 * HW);
    int start4 = sub * CHUNK4;

    float acc = 0.0f;
    #pragma unroll 2
    for (int i = threadIdx.x; i < CHUNK4; i += 256) {
        int p4 = start4 + i;
        float4 r  = __ldcs(&base[p4]);
        float4 g  = __ldcs(&base[p4 + HW4]);
        float4 bl = __ldcs(&base[p4 + 2 * HW4]);
        float rr = __saturatef(r.x * bf) + __saturatef(r.y * bf)
                 + __saturatef(r.z * bf) + __saturatef(r.w * bf);
        float gg = __saturatef(g.x * bf) + __saturatef(g.y * bf)
                 + __saturatef(g.z * bf) + __saturatef(g.w * bf);
        float bb = __saturatef(bl.x * bf) + __saturatef(bl.y * bf)
                 + __saturatef(bl.z * bf) + __saturatef(bl.w * bf);
        acc += 0.299f * rr + 0.587f * gg + 0.114f * bb;
    }

    __shared__ float s[256];
    s[threadIdx.x] = acc;
    __syncthreads();
    #pragma unroll
    for (int off = 128; off > 0; off >>= 1) {
        if (threadIdx.x < off) s[threadIdx.x] += s[threadIdx.x + off];
        __syncthreads();
    }
    if (threadIdx.x == 0) g_partial[blk] = s[0];
}

// ---------------- Pass 2: fused brightness/contrast/saturation/hue ----------------
__device__ __forceinline__ void px_proc(float r, float g, float bl,
                                        float bf, float cf, float sf, float hf,
                                        float mean,
                                        float& ro, float& go, float& bo)
{
    // brightness
    r  = __saturatef(r * bf);
    g  = __saturatef(g * bf);
    bl = __saturatef(bl * bf);
    // contrast (blend with per-batch mean gray)
    float omcf = 1.0f - cf;
    r  = __saturatef(cf * r + omcf * mean);
    g  = __saturatef(cf * g + omcf * mean);
    bl = __saturatef(cf * bl + omcf * mean);
    // saturation (blend with per-pixel gray)
    float gray = 0.299f * r + 0.587f * g + 0.114f * bl;
    float omsf = 1.0f - sf;
    r  = __saturatef(sf * r + omsf * gray);
    g  = __saturatef(sf * g + omsf * gray);
    bl = __saturatef(sf * bl + omsf * gray);
    // hue: RGB -> HSV
    float maxc = fmaxf(r, fmaxf(g, bl));
    float minc = fminf(r, fminf(g, bl));
    float v = maxc;
    float cr = maxc - minc;
    float crd = (cr == 0.0f) ? 1.0f : cr;
    float s = cr / ((maxc == 0.0f) ? 1.0f : maxc);
    float inv_crd = 1.0f / crd;
    float rc = (maxc - r) * inv_crd;
    float gc = (maxc - g) * inv_crd;
    float bc = (maxc - bl) * inv_crd;
    float h;
    if (maxc == r)       h = bc - gc;            // hr branch
    else if (maxc == g)  h = 2.0f + rc - bc;     // hg branch (maxc != r here)
    else                 h = 4.0f + gc - rc;     // hb branch
    h = h * (1.0f / 6.0f);
    h = h - floorf(h);        // python-style mod 1
    h = h + hf;
    h = h - floorf(h);
    // HSV -> RGB
    float i6 = h * 6.0f;
    float fi = floorf(i6);
    float f = i6 - fi;
    int i = ((int)fi) % 6;    // guards h==1.0 rounding edge
    float p = v * (1.0f - s);
    float q = v * (1.0f - f * s);
    float t = v * (1.0f - (1.0f - f) * s);
    switch (i) {
        case 0:  ro = v; go = t; bo = p; break;
        case 1:  ro = q; go = v; bo = p; break;
        case 2:  ro = p; go = v; bo = t; break;
        case 3:  ro = p; go = q; bo = v; break;
        case 4:  ro = t; go = p; bo = v; break;
        default: ro = v; go = p; bo = q; break;
    }
}

__global__ void __launch_bounds__(256)
cr_main_kernel(const float* __restrict__ x,
               const float* __restrict__ bf_arr,
               const float* __restrict__ cf_arr,
               const float* __restrict__ sf_arr,
               const float* __restrict__ hf_arr,
               float* __restrict__ out)
{
    int b = blockIdx.x / BLKS_PER_BATCH;           // uniform per block
    int local4 = (blockIdx.x % BLKS_PER_BATCH) * 256 + threadIdx.x;

    __shared__ float sm[5];
    if (threadIdx.x == 0) {
        float s = 0.0f;
        #pragma unroll
        for (int i = 0; i < NBLK; i++) s += g_partial[b * NBLK + i];
        sm[0] = s * (1.0f / (float)HW);
        sm[1] = bf_arr[b];
        sm[2] = cf_arr[b];
        sm[3] = sf_arr[b];
        sm[4] = hf_arr[b];
    }
    __syncthreads();
    float mean = sm[0], bf = sm[1], cf = sm[2], sf = sm[3], hf = sm[4];

    size_t base = (size_t)b * 3 * HW;
    const float4* px  = (const float4*)(x + base);
    float4*       pox = (float4*)(out + base);

    float4 R  = __ldcs(&px[local4]);
    float4 G  = __ldcs(&px[local4 + HW4]);
    float4 Bv = __ldcs(&px[local4 + 2 * HW4]);

    float4 Ro, Go, Bo;
    px_proc(R.x, G.x, Bv.x, bf, cf, sf, hf, mean, Ro.x, Go.x, Bo.x);
    px_proc(R.y, G.y, Bv.y, bf, cf, sf, hf, mean, Ro.y, Go.y, Bo.y);
    px_proc(R.z, G.z, Bv.z, bf, cf, sf, hf, mean, Ro.z, Go.z, Bo.z);
    px_proc(R.w, G.w, Bv.w, bf, cf, sf, hf, mean, Ro.w, Go.w, Bo.w);

    __stcs(&pox[local4],           Ro);
    __stcs(&pox[local4 + HW4],     Go);
    __stcs(&pox[local4 + 2 * HW4], Bo);
}

extern "C" void kernel_launch(void* const* d_in, const int* in_sizes, int n_in,
                              void* d_out, int out_size)
{
    const float* x  = (const float*)d_in[0];
    const float* bf = (const float*)d_in[1];
    const float* cf = (const float*)d_in[2];
    const float* sf = (const float*)d_in[3];
    const float* hf = (const float*)d_in[4];
    float* out = (float*)d_out;

    cr_reduce_kernel<<<BATCH * NBLK, 256>>>(x, bf);
    cr_main_kernel<<<BATCH * BLKS_PER_BATCH, 256>>>(x, bf, cf, sf, hf, out);
}

// round 4
// speedup vs baseline: 1.3451x; 1.1728x over previous
#include <cuda_runtime.h>

#define BATCH 32
#define HW 307200            // 480*640
#define HW4 (HW/4)           // 76800 float4 per channel per batch
#define NBLK 50              // reduction blocks per batch -> 1600 total
#define CHUNK4 (HW4/NBLK)    // 1536 float4 per reduction block (6 iters/thread, no tail)
#define BLKS_PER_BATCH 300   // HW4 / 256

__device__ float g_partial[BATCH * NBLK];

// ---------------- Pass 1: per-batch gray sum of clip(x*bf) ----------------
__global__ void __launch_bounds__(256)
cr_reduce_kernel(const float* __restrict__ x, const float* __restrict__ bf_arr)
{
    int blk = blockIdx.x;          // 0 .. BATCH*NBLK-1
    int b   = blk / NBLK;
    int sub = blk % NBLK;
    float bf = bf_arr[b];

    const float4* base = (const float4*)(x + (size_t)b * 3 * HW);
    int start4 = sub * CHUNK4;

    float acc = 0.0f;
    #pragma unroll 2
    for (int i = threadIdx.x; i < CHUNK4; i += 256) {
        int p4 = start4 + i;
        float4 r  = __ldcs(&base[p4]);
        float4 g  = __ldcs(&base[p4 + HW4]);
        float4 bl = __ldcs(&base[p4 + 2 * HW4]);
        float rr = __saturatef(r.x * bf) + __saturatef(r.y * bf)
                 + __saturatef(r.z * bf) + __saturatef(r.w * bf);
        float gg = __saturatef(g.x * bf) + __saturatef(g.y * bf)
                 + __saturatef(g.z * bf) + __saturatef(g.w * bf);
        float bb = __saturatef(bl.x * bf) + __saturatef(bl.y * bf)
                 + __saturatef(bl.z * bf) + __saturatef(bl.w * bf);
        acc += 0.299f * rr + 0.587f * gg + 0.114f * bb;
    }

    __shared__ float s[256];
    s[threadIdx.x] = acc;
    __syncthreads();
    #pragma unroll
    for (int off = 128; off > 0; off >>= 1) {
        if (threadIdx.x < off) s[threadIdx.x] += s[threadIdx.x + off];
        __syncthreads();
    }
    if (threadIdx.x == 0) g_partial[blk] = s[0];
}

// ---------------- Pass 2: fused brightness/contrast/saturation/hue ----------------
// Branchless hue: out_n = v - cr * sat(min(k, 4-k)), k = (n + 6h) mod 6, n={5,3,1}.
// Uses v*s == cr identity (holds incl. maxc==0 case) -> no 's', no second division.
__device__ __forceinline__ void px_proc(float r, float g, float bl,
                                        float bf, float cf, float cmean,
                                        float sf, float hf,
                                        float& ro, float& go, float& bo)
{
    // brightness
    r  = __saturatef(r * bf);
    g  = __saturatef(g * bf);
    bl = __saturatef(bl * bf);
    // contrast (cmean = (1-cf)*mean, precomputed)
    r  = __saturatef(fmaf(cf, r,  cmean));
    g  = __saturatef(fmaf(cf, g,  cmean));
    bl = __saturatef(fmaf(cf, bl, cmean));
    // saturation
    float gray = 0.299f * r + 0.587f * g + 0.114f * bl;
    float gm = (1.0f - sf) * gray;
    r  = __saturatef(fmaf(sf, r,  gm));
    g  = __saturatef(fmaf(sf, g,  gm));
    bl = __saturatef(fmaf(sf, bl, gm));
    // hue: RGB -> "h6" (hue in sector units, before mod)
    float maxc = fmaxf(r, fmaxf(g, bl));
    float minc = fminf(r, fminf(g, bl));
    float cr = maxc - minc;
    float crd = (cr == 0.0f) ? 1.0f : cr;
    float inv = __fdividef(1.0f, crd);
    // bc-gc = (g-b)/crd ; 2+rc-bc = 2+(b-r)/crd ; 4+gc-rc = 4+(r-g)/crd
    float num, off;
    if (maxc == r)      { num = g - bl;  off = 0.0f; }
    else if (maxc == g) { num = bl - r;  off = 2.0f; }
    else                { num = r - g;   off = 4.0f; }
    float h6r = fmaf(num, inv, off);
    // h = frac(h6r/6 + hf)  (frac(frac(x)+hf) == frac(x+hf))
    float hh = fmaf(h6r, 0.166666672f, hf);
    hh = hh - floorf(hh);
    float h6 = hh * 6.0f;
    // HSV -> RGB, branchless
    float kr = 5.0f + h6; kr = (kr >= 6.0f) ? kr - 6.0f : kr;
    float kg = 3.0f + h6; kg = (kg >= 6.0f) ? kg - 6.0f : kg;
    float kb = 1.0f + h6; kb = (kb >= 6.0f) ? kb - 6.0f : kb;
    float wr = __saturatef(fminf(kr, 4.0f - kr));
    float wg = __saturatef(fminf(kg, 4.0f - kg));
    float wb = __saturatef(fminf(kb, 4.0f - kb));
    ro = fmaf(-wr, cr, maxc);
    go = fmaf(-wg, cr, maxc);
    bo = fmaf(-wb, cr, maxc);
}

__global__ void __launch_bounds__(256)
cr_main_kernel(const float* __restrict__ x,
               const float* __restrict__ bf_arr,
               const float* __restrict__ cf_arr,
               const float* __restrict__ sf_arr,
               const float* __restrict__ hf_arr,
               float* __restrict__ out)
{
    int b = blockIdx.x / BLKS_PER_BATCH;           // uniform per block
    int local4 = (blockIdx.x % BLKS_PER_BATCH) * 256 + threadIdx.x;

    __shared__ float sm[5];
    if (threadIdx.x == 0) {
        float s = 0.0f;
        #pragma unroll
        for (int i = 0; i < NBLK; i++) s += g_partial[b * NBLK + i];
        float mean = s * (1.0f / (float)HW);
        float cf = cf_arr[b];
        sm[0] = (1.0f - cf) * mean;   // cmean
        sm[1] = bf_arr[b];
        sm[2] = cf;
        sm[3] = sf_arr[b];
        sm[4] = hf_arr[b];
    }
    __syncthreads();
    float cmean = sm[0], bf = sm[1], cf = sm[2], sf = sm[3], hf = sm[4];

    size_t base = (size_t)b * 3 * HW;
    const float4* px  = (const float4*)(x + base);
    float4*       pox = (float4*)(out + base);

    float4 R  = px[local4];
    float4 G  = px[local4 + HW4];
    float4 Bv = px[local4 + 2 * HW4];

    float4 Ro, Go, Bo;
    px_proc(R.x, G.x, Bv.x, bf, cf, cmean, sf, hf, Ro.x, Go.x, Bo.x);
    px_proc(R.y, G.y, Bv.y, bf, cf, cmean, sf, hf, Ro.y, Go.y, Bo.y);
    px_proc(R.z, G.z, Bv.z, bf, cf, cmean, sf, hf, Ro.z, Go.z, Bo.z);
    px_proc(R.w, G.w, Bv.w, bf, cf, cmean, sf, hf, Ro.w, Go.w, Bo.w);

    pox[local4]           = Ro;
    pox[local4 + HW4]     = Go;
    pox[local4 + 2 * HW4] = Bo;
}

extern "C" void kernel_launch(void* const* d_in, const int* in_sizes, int n_in,
                              void* d_out, int out_size)
{
    const float* x  = (const float*)d_in[0];
    const float* bf = (const float*)d_in[1];
    const float* cf = (const float*)d_in[2];
    const float* sf = (const float*)d_in[3];
    const float* hf = (const float*)d_in[4];
    float* out = (float*)d_out;

    cr_reduce_kernel<<<BATCH * NBLK, 256>>>(x, bf);
    cr_main_kernel<<<BATCH * BLKS_PER_BATCH, 256>>>(x, bf, cf, sf, hf, out);
}

// round 8
// speedup vs baseline: 1.3844x; 1.0292x over previous
#include <cuda_runtime.h>

#define BATCH 32
#define HW 307200            // 480*640
#define HW4 (HW/4)           // 76800 float4 per channel per batch
#define NBLK 75              // reduction blocks per batch -> 2400 total (2 clean waves)
#define CHUNK4 1024          // 76800/75 ; 4 iters/thread exactly
#define BLKS_PER_BATCH 300   // HW4 / 256

__device__ float g_partial[BATCH * NBLK];

// ---------------- Pass 1: per-batch gray sum of clip(x*bf) ----------------
__global__ void __launch_bounds__(256)
cr_reduce_kernel(const float* __restrict__ x, const float* __restrict__ bf_arr)
{
    int blk = blockIdx.x;          // 0 .. BATCH*NBLK-1
    int b   = blk / NBLK;
    int sub = blk % NBLK;
    float bf = bf_arr[b];

    const float4* base = (const float4*)(x + (size_t)b * 3 * HW);
    int start4 = sub * CHUNK4 + threadIdx.x;

    float acc = 0.0f;
    #pragma unroll
    for (int it = 0; it < 4; it++) {
        int p4 = start4 + it * 256;
        float4 r  = __ldcs(&base[p4]);
        float4 g  = __ldcs(&base[p4 + HW4]);
        float4 bl = __ldcs(&base[p4 + 2 * HW4]);
        float rr = __saturatef(r.x * bf) + __saturatef(r.y * bf)
                 + __saturatef(r.z * bf) + __saturatef(r.w * bf);
        float gg = __saturatef(g.x * bf) + __saturatef(g.y * bf)
                 + __saturatef(g.z * bf) + __saturatef(g.w * bf);
        float bb = __saturatef(bl.x * bf) + __saturatef(bl.y * bf)
                 + __saturatef(bl.z * bf) + __saturatef(bl.w * bf);
        acc += 0.299f * rr + 0.587f * gg + 0.114f * bb;
    }

    // warp reduce
    #pragma unroll
    for (int off = 16; off > 0; off >>= 1)
        acc += __shfl_down_sync(0xFFFFFFFFu, acc, off);

    __shared__ float s[8];
    int lane = threadIdx.x & 31, wid = threadIdx.x >> 5;
    if (lane == 0) s[wid] = acc;
    __syncthreads();
    if (wid == 0) {
        float v = (lane < 8) ? s[lane] : 0.0f;
        #pragma unroll
        for (int off = 4; off > 0; off >>= 1)
            v += __shfl_down_sync(0xFFFFFFFFu, v, off);
        if (lane == 0) g_partial[blk] = v;
    }
}

// ---------------- Pass 2: fused brightness/contrast/saturation/hue ----------------
// Branchless hue: out_n = v - cr * sat(min(k, 4-k)), k = (n + 6h) mod 6, n={5,3,1}.
__device__ __forceinline__ void px_proc(float r, float g, float bl,
                                        float bf, float cf, float cmean,
                                        float sf, float hf,
                                        float& ro, float& go, float& bo)
{
    r  = __saturatef(r * bf);
    g  = __saturatef(g * bf);
    bl = __saturatef(bl * bf);
    r  = __saturatef(fmaf(cf, r,  cmean));
    g  = __saturatef(fmaf(cf, g,  cmean));
    bl = __saturatef(fmaf(cf, bl, cmean));
    float gray = 0.299f * r + 0.587f * g + 0.114f * bl;
    float gm = (1.0f - sf) * gray;
    r  = __saturatef(fmaf(sf, r,  gm));
    g  = __saturatef(fmaf(sf, g,  gm));
    bl = __saturatef(fmaf(sf, bl, gm));
    float maxc = fmaxf(r, fmaxf(g, bl));
    float minc = fminf(r, fminf(g, bl));
    float cr = maxc - minc;
    float crd = (cr == 0.0f) ? 1.0f : cr;
    float inv = __fdividef(1.0f, crd);
    float num, off;
    if (maxc == r)      { num = g - bl;  off = 0.0f; }
    else if (maxc == g) { num = bl - r;  off = 2.0f; }
    else                { num = r - g;   off = 4.0f; }
    float h6r = fmaf(num, inv, off);
    float hh = fmaf(h6r, 0.166666672f, hf);
    hh = hh - floorf(hh);
    float h6 = hh * 6.0f;
    float kr = 5.0f + h6; kr = (kr >= 6.0f) ? kr - 6.0f : kr;
    float kg = 3.0f + h6; kg = (kg >= 6.0f) ? kg - 6.0f : kg;
    float kb = 1.0f + h6; kb = (kb >= 6.0f) ? kb - 6.0f : kb;
    float wr = __saturatef(fminf(kr, 4.0f - kr));
    float wg = __saturatef(fminf(kg, 4.0f - kg));
    float wb = __saturatef(fminf(kb, 4.0f - kb));
    ro = fmaf(-wr, cr, maxc);
    go = fmaf(-wg, cr, maxc);
    bo = fmaf(-wb, cr, maxc);
}

__global__ void __launch_bounds__(256)
cr_main_kernel(const float* __restrict__ x,
               const float* __restrict__ bf_arr,
               const float* __restrict__ cf_arr,
               const float* __restrict__ sf_arr,
               const float* __restrict__ hf_arr,
               float* __restrict__ out)
{
    int b = blockIdx.x / BLKS_PER_BATCH;           // uniform per block
    int local4 = (blockIdx.x % BLKS_PER_BATCH) * 256 + threadIdx.x;

    __shared__ float sm[5];
    if (threadIdx.x < 32) {
        float v = 0.0f;
        for (int i = threadIdx.x; i < NBLK; i += 32) v += g_partial[b * NBLK + i];
        #pragma unroll
        for (int off = 16; off > 0; off >>= 1)
            v += __shfl_down_sync(0xFFFFFFFFu, v, off);
        if (threadIdx.x == 0) {
            float mean = v * (1.0f / (float)HW);
            float cf = cf_arr[b];
            sm[0] = (1.0f - cf) * mean;   // cmean
            sm[1] = bf_arr[b];
            sm[2] = cf;
            sm[3] = sf_arr[b];
            sm[4] = hf_arr[b];
        }
    }
    __syncthreads();
    float cmean = sm[0], bf = sm[1], cf = sm[2], sf = sm[3], hf = sm[4];

    size_t base = (size_t)b * 3 * HW;
    const float4* px  = (const float4*)(x + base);
    float4*       pox = (float4*)(out + base);

    float4 R  = px[local4];
    float4 G  = px[local4 + HW4];
    float4 Bv = px[local4 + 2 * HW4];

    float4 Ro, Go, Bo;
    px_proc(R.x, G.x, Bv.x, bf, cf, cmean, sf, hf, Ro.x, Go.x, Bo.x);
    px_proc(R.y, G.y, Bv.y, bf, cf, cmean, sf, hf, Ro.y, Go.y, Bo.y);
    px_proc(R.z, G.z, Bv.z, bf, cf, cmean, sf, hf, Ro.z, Go.z, Bo.z);
    px_proc(R.w, G.w, Bv.w, bf, cf, cmean, sf, hf, Ro.w, Go.w, Bo.w);

    pox[local4]           = Ro;
    pox[local4 + HW4]     = Go;
    pox[local4 + 2 * HW4] = Bo;
}

extern "C" void kernel_launch(void* const* d_in, const int* in_sizes, int n_in,
                              void* d_out, int out_size)
{
    const float* x  = (const float*)d_in[0];
    const float* bf = (const float*)d_in[1];
    const float* cf = (const float*)d_in[2];
    const float* sf = (const float*)d_in[3];
    const float* hf = (const float*)d_in[4];
    float* out = (float*)d_out;

    cr_reduce_kernel<<<BATCH * NBLK, 256>>>(x, bf);
    cr_main_kernel<<<BATCH * BLKS_PER_BATCH, 256>>>(x, bf, cf, sf, hf, out);
}